// round 16
// baseline (speedup 1.0000x reference)
#include <cuda_runtime.h>
#include <cuda_fp16.h>
#include <cstdint>

#define CD 1024
#define BD 4
#define TD 2048
#define NH 16
#define HD 64
#define MD (BD*TD)   // 8192 rows

// Scratch (__device__ globals; allocation-free rule). fp16.
__device__ __half g_xh[(size_t)MD * CD];
__device__ __half g_qh[(size_t)MD * CD];
__device__ __half g_kh[(size_t)MD * CD];
__device__ __half g_vh[(size_t)MD * CD];
__device__ __half g_oh[(size_t)MD * CD];
__device__ __half g_wh[4ull * CD * CD];

// ---------------------------------------------------------------------------
// helpers
// ---------------------------------------------------------------------------
__device__ __forceinline__ void cp_async16(uint32_t s, const void* g) {
    asm volatile("cp.async.cg.shared.global [%0], [%1], 16;\n" :: "r"(s), "l"(g));
}
__device__ __forceinline__ void cp_commit() {
    asm volatile("cp.async.commit_group;\n");
}
template <int N>
__device__ __forceinline__ void cp_waitn() {
    asm volatile("cp.async.wait_group %0;\n" :: "n"(N));
}
__device__ __forceinline__ void ldsm4(uint32_t* r, uint32_t a) {
    asm volatile("ldmatrix.sync.aligned.m8n8.x4.shared.b16 {%0,%1,%2,%3}, [%4];\n"
                 : "=r"(r[0]), "=r"(r[1]), "=r"(r[2]), "=r"(r[3]) : "r"(a));
}
__device__ __forceinline__ void ldsm4t(uint32_t* r, uint32_t a) {
    asm volatile("ldmatrix.sync.aligned.m8n8.x4.trans.shared.b16 {%0,%1,%2,%3}, [%4];\n"
                 : "=r"(r[0]), "=r"(r[1]), "=r"(r[2]), "=r"(r[3]) : "r"(a));
}
__device__ __forceinline__ void mma16816(float* c, const uint32_t* a,
                                         uint32_t b0, uint32_t b1) {
    asm volatile(
        "mma.sync.aligned.m16n8k16.row.col.f32.f16.f16.f32 "
        "{%0,%1,%2,%3},{%4,%5,%6,%7},{%8,%9},{%0,%1,%2,%3};\n"
        : "+f"(c[0]), "+f"(c[1]), "+f"(c[2]), "+f"(c[3])
        : "r"(a[0]), "r"(a[1]), "r"(a[2]), "r"(a[3]), "r"(b0), "r"(b1));
}
__device__ __forceinline__ uint32_t pack_f16(float a, float b) {
    __half2 v = __floats2half2_rn(a, b);
    return *reinterpret_cast<uint32_t*>(&v);
}
__device__ __forceinline__ float fexp2(float x) {
    float y;
    asm("ex2.approx.ftz.f32 %0, %1;" : "=f"(y) : "f"(x));
    return y;
}

// ---------------------------------------------------------------------------
// fp32 -> fp16 converts: x (single tensor) and all four weights (fused).
// ---------------------------------------------------------------------------
__global__ void conv_kernel(const float* __restrict__ in,
                            __half* __restrict__ out, int n4) {
    int i = blockIdx.x * blockDim.x + threadIdx.x;
    if (i >= n4) return;
    float4 v = ((const float4*)in)[i];
    ((uint32_t*)out)[2 * i]     = pack_f16(v.x, v.y);
    ((uint32_t*)out)[2 * i + 1] = pack_f16(v.z, v.w);
}
// 4 weights, 1024 blocks each (CC/4 = 262144 chunks = 1024 * 256)
__global__ void conv4_kernel(const float* __restrict__ w0,
                             const float* __restrict__ w1,
                             const float* __restrict__ w2,
                             const float* __restrict__ w3,
                             __half* __restrict__ out) {
    const int which = blockIdx.x >> 10;
    const int j = (blockIdx.x & 1023) * 256 + threadIdx.x;
    const float* in = (which == 0) ? w0 : (which == 1) ? w1 :
                      (which == 2) ? w2 : w3;
    float4 v = ((const float4*)in)[j];
    __half* o = out + (size_t)which * CD * CD;
    ((uint32_t*)o)[2 * j]     = pack_f16(v.x, v.y);
    ((uint32_t*)o)[2 * j + 1] = pack_f16(v.z, v.w);
}

// ---------------------------------------------------------------------------
// Plain fp16 GEMM (1 MMA/step), 3-stage cp.async pipeline (prefetch dist 2).
//   OM=0: fused QKV — blockIdx.x>>3 selects Q/K/V, fp16 out
//   OM=1: Wo        — fp32 out to the harness buffer
// CTA 128x128x32, 8 warps (warp tile 32x64).
// ---------------------------------------------------------------------------
#define TSTRIDE 40
#define TILE_H (128 * TSTRIDE)
#define STAGE2_H (2 * TILE_H)          // A, W
#define QSMEM (3 * STAGE2_H * 2)       // 61440 bytes (3 stages)

template <int OM>
__global__ void __launch_bounds__(256, 2) gemm_f16(
    const __half* __restrict__ X, const __half* __restrict__ Wall,
    __half* __restrict__ Qh, __half* __restrict__ Kh, __half* __restrict__ Vh,
    float* __restrict__ C) {
    extern __shared__ __align__(16) __half sm_g[];
    const uint32_t sbase = (uint32_t)__cvta_generic_to_shared(sm_g);
    const int tid = threadIdx.x;
    const int lane = tid & 31, warp = tid >> 5;
    const int wm = warp >> 1, wn = warp & 1;
    const int which = (OM == 0) ? (blockIdx.x >> 3) : 0;
    const int n0 = (OM == 0) ? (blockIdx.x & 7) * 128 : blockIdx.x * 128;
    const int m0 = blockIdx.y * 128;

    const int lrow = tid >> 2;
    const int lch = (tid & 3) * 8;
    const __half* gp[2] = {
        X + (size_t)(m0 + lrow) * CD + lch,
        Wall + (size_t)which * CD * CD + (size_t)(n0 + lrow) * CD + lch};
    const uint32_t s_off = (uint32_t)(lrow * TSTRIDE + lch) * 2;

    const int lrow_a = (lane & 7) + ((lane >> 3) & 1) * 8;
    const int kca = (lane >> 4) * 8;
    const int lrow_b = (lane & 7) + (lane >> 4) * 8;
    const int kcb = ((lane >> 3) & 1) * 8;

    float acc[2][8][4];
    #pragma unroll
    for (int i = 0; i < 2; i++)
        #pragma unroll
        for (int j = 0; j < 8; j++)
            #pragma unroll
            for (int q = 0; q < 4; q++) acc[i][j][q] = 0.f;

    auto load_stage = [&](int s, int k0) {
        uint32_t so = sbase + (uint32_t)(s * STAGE2_H) * 2;
        #pragma unroll
        for (int t = 0; t < 2; t++) {
            const __half* g = gp[t] + k0;
            uint32_t sa = so + (uint32_t)(t * TILE_H) * 2 + s_off;
            cp_async16(sa, g);
            cp_async16(sa + 64 * TSTRIDE * 2, g + (size_t)64 * CD);
        }
        cp_commit();
    };

    load_stage(0, 0);
    load_stage(1, 32);

    const int NIT = CD / 32;
    for (int it = 0; it < NIT; it++) {
        if (it + 1 < NIT) cp_waitn<1>(); else cp_waitn<0>();
        __syncthreads();
        if (it + 2 < NIT) load_stage((it + 2) % 3, (it + 2) * 32);
        uint32_t so = sbase + (uint32_t)((it % 3) * STAGE2_H) * 2;
        #pragma unroll
        for (int ks = 0; ks < 2; ks++) {
            const int k0h = ks * 16;
            uint32_t ah[2][4];
            #pragma unroll
            for (int mt = 0; mt < 2; mt++) {
                int row = wm * 32 + mt * 16 + lrow_a;
                ldsm4(ah[mt], so + (uint32_t)(row * TSTRIDE + k0h + kca) * 2);
            }
            uint32_t bw[4][4];
            #pragma unroll
            for (int j = 0; j < 4; j++) {
                int nr = wn * 64 + j * 16 + lrow_b;
                ldsm4(bw[j], so + (uint32_t)(TILE_H + nr * TSTRIDE + k0h + kcb) * 2);
            }
            #pragma unroll
            for (int mt = 0; mt < 2; mt++)
                #pragma unroll
                for (int j = 0; j < 4; j++) {
                    mma16816(acc[mt][2 * j],     ah[mt], bw[j][0], bw[j][1]);
                    mma16816(acc[mt][2 * j + 1], ah[mt], bw[j][2], bw[j][3]);
                }
        }
    }

    const int cr = lane >> 2, cc = (lane & 3) * 2;
    if (OM == 0) {
        __half* D = (which == 0) ? Qh : (which == 1) ? Kh : Vh;
        #pragma unroll
        for (int mt = 0; mt < 2; mt++) {
            int r = m0 + wm * 32 + mt * 16 + cr;
            #pragma unroll
            for (int nt = 0; nt < 8; nt++) {
                int col = n0 + wn * 64 + nt * 8 + cc;
                *(uint32_t*)&D[(size_t)r * CD + col] =
                    pack_f16(acc[mt][nt][0], acc[mt][nt][1]);
                *(uint32_t*)&D[(size_t)(r + 8) * CD + col] =
                    pack_f16(acc[mt][nt][2], acc[mt][nt][3]);
            }
        }
    } else {
        #pragma unroll
        for (int mt = 0; mt < 2; mt++) {
            int r = m0 + wm * 32 + mt * 16 + cr;
            #pragma unroll
            for (int nt = 0; nt < 8; nt++) {
                int col = n0 + wn * 64 + nt * 8 + cc;
                *(float2*)&C[(size_t)r * CD + col] =
                    make_float2(acc[mt][nt][0], acc[mt][nt][1]);
                *(float2*)&C[(size_t)(r + 8) * CD + col] =
                    make_float2(acc[mt][nt][2], acc[mt][nt][3]);
            }
        }
    }
}

// ---------------------------------------------------------------------------
// Flash attention (causal), fp16 tensor cores. Q/K/V/P/O single fp16,
// fp32 accumulators, exp2-domain softmax.
// 3-stage KV pipeline (prefetch distance 2): Q staged in slot 2, KV tiles
// 0 and 1 in flight before the Q-fragment reads. CTA = 128 q-rows (8 warps
// x 16), KV tile 64, 2 CTAs/SM.
// ---------------------------------------------------------------------------
#define ATS 72                     // smem row stride (halves)
#define ATILE (64 * ATS)           // halves per 64-row tile
#define ASTAGE (2 * ATILE)         // Kh, Vh
#define ATT_SMEM (3 * ASTAGE * 2)  // 55296 bytes (3 stages)
#define SCL2 0.18033688f           // 0.125 * log2(e)

__global__ void __launch_bounds__(256, 2) attn_mma(
    const __half* __restrict__ Qh, const __half* __restrict__ Kh,
    const __half* __restrict__ Vh, __half* __restrict__ Oh) {
    extern __shared__ __align__(16) __half sm_a[];
    const uint32_t sb = (uint32_t)__cvta_generic_to_shared(sm_a);
    const int tid = threadIdx.x;
    const int lane = tid & 31, warp = tid >> 5;
    const int qb = gridDim.x - 1 - blockIdx.x;     // heavy blocks first
    const int i0 = qb * 128;
    const int bh = blockIdx.y;
    const int b = bh >> 4, h = bh & 15;
    const size_t grow = (size_t)b * TD;
    const int gcol = h * HD;

    const int lra = (lane & 7) + ((lane >> 3) & 1) * 8;
    const int kca = (lane >> 4) * 8;
    const int lrb = (lane & 7) + (lane >> 4) * 8;
    const int kcb = ((lane >> 3) & 1) * 8;

    const int nit = qb * 2 + 2;

    // KV tile it -> stage it % 3
    auto load_kv = [&](int it) {
        uint32_t so = sb + (uint32_t)((it % 3) * ASTAGE) * 2;
        int j0 = it * 64;
        #pragma unroll
        for (int k = 0; k < 2; k++) {
            int c = tid + k * 256;                 // 512 chunks per tile
            int row = c >> 3, colh = (c & 7) * 8;
            size_t g = (grow + j0 + row) * CD + gcol + colh;
            uint32_t sa = so + (uint32_t)(row * ATS + colh) * 2;
            cp_async16(sa, Kh + g);
            cp_async16(sa + ATILE * 2, Vh + g);
        }
        cp_commit();
    };

    // ---- stage Q (128 x 64) into slot 2, then prefetch KV tiles 0 and 1 ----
    {
        const uint32_t qbase = sb + (uint32_t)(2 * ASTAGE) * 2;
        #pragma unroll
        for (int k = 0; k < 4; k++) {
            int c = tid + k * 256;                 // 1024 chunks
            int row = c >> 3, colh = (c & 7) * 8;
            size_t g = (grow + i0 + row) * CD + gcol + colh;
            cp_async16(qbase + (uint32_t)(row * ATS + colh) * 2, Qh + g);
        }
        cp_commit();
    }
    load_kv(0);
    load_kv(1);                        // nit >= 2 always, both consumed

    cp_waitn<2>();                     // retires the Q group (in-order)
    __syncthreads();

    uint32_t qf[4][4];
    {
        const uint32_t qbase = sb + (uint32_t)(2 * ASTAGE) * 2;
        int row = warp * 16 + lra;
        #pragma unroll
        for (int kt = 0; kt < 4; kt++)
            ldsm4(qf[kt], qbase + (uint32_t)(row * ATS + kt * 16 + kca) * 2);
    }
    // kv2 (slot 2) is only prefetched after the it=0 barrier below, which
    // all warps reach only after their qf reads — no extra sync needed.

    float o[8][4];
    #pragma unroll
    for (int j = 0; j < 8; j++)
        #pragma unroll
        for (int q = 0; q < 4; q++) o[j][q] = 0.f;
    float m0r = -1e30f, m1r = -1e30f, l0r = 0.f, l1r = 0.f;

    const int wrow = i0 + warp * 16;

    for (int it = 0; it < nit; it++) {
        if (it + 1 < nit) cp_waitn<1>(); else cp_waitn<0>();
        __syncthreads();
        if (it + 2 < nit) load_kv(it + 2);
        uint32_t so = sb + (uint32_t)((it % 3) * ASTAGE) * 2;
        const int j0 = it * 64;

        // ---- S = Q K^T ----
        float s[8][4];
        #pragma unroll
        for (int j = 0; j < 8; j++)
            #pragma unroll
            for (int q = 0; q < 4; q++) s[j][q] = 0.f;

        #pragma unroll
        for (int kt = 0; kt < 4; kt++) {
            #pragma unroll
            for (int jp = 0; jp < 4; jp++) {
                uint32_t a = so + (uint32_t)((jp * 16 + lrb) * ATS + kt * 16 + kcb) * 2;
                uint32_t b4[4];
                ldsm4(b4, a);
                mma16816(s[2 * jp],     qf[kt], b4[0], b4[1]);
                mma16816(s[2 * jp + 1], qf[kt], b4[2], b4[3]);
            }
        }

        // ---- scale (exp2 domain) + causal mask ----
        const int r0 = wrow + (lane >> 2);
        const int r1 = r0 + 8;
        const bool domask = (j0 + 63) > wrow;
        #pragma unroll
        for (int j = 0; j < 8; j++) {
            int c0 = j0 + j * 8 + (lane & 3) * 2;
            #pragma unroll
            for (int q = 0; q < 4; q++) {
                float sv = s[j][q] * SCL2;
                if (domask) {
                    int col = c0 + (q & 1);
                    int row = (q < 2) ? r0 : r1;
                    if (col > row) sv = -1e30f;
                }
                s[j][q] = sv;
            }
        }

        // ---- online softmax (base-2) ----
        float mx0 = -1e30f, mx1 = -1e30f;
        #pragma unroll
        for (int j = 0; j < 8; j++) {
            mx0 = fmaxf(mx0, fmaxf(s[j][0], s[j][1]));
            mx1 = fmaxf(mx1, fmaxf(s[j][2], s[j][3]));
        }
        mx0 = fmaxf(mx0, __shfl_xor_sync(0xffffffffu, mx0, 1));
        mx0 = fmaxf(mx0, __shfl_xor_sync(0xffffffffu, mx0, 2));
        mx1 = fmaxf(mx1, __shfl_xor_sync(0xffffffffu, mx1, 1));
        mx1 = fmaxf(mx1, __shfl_xor_sync(0xffffffffu, mx1, 2));
        float mn0 = fmaxf(m0r, mx0), mn1 = fmaxf(m1r, mx1);
        float corr0 = fexp2(m0r - mn0), corr1 = fexp2(m1r - mn1);
        float rs0 = 0.f, rs1 = 0.f;
        #pragma unroll
        for (int j = 0; j < 8; j++) {
            s[j][0] = fexp2(s[j][0] - mn0);
            s[j][1] = fexp2(s[j][1] - mn0);
            s[j][2] = fexp2(s[j][2] - mn1);
            s[j][3] = fexp2(s[j][3] - mn1);
            rs0 += s[j][0] + s[j][1];
            rs1 += s[j][2] + s[j][3];
        }
        rs0 += __shfl_xor_sync(0xffffffffu, rs0, 1);
        rs0 += __shfl_xor_sync(0xffffffffu, rs0, 2);
        rs1 += __shfl_xor_sync(0xffffffffu, rs1, 1);
        rs1 += __shfl_xor_sync(0xffffffffu, rs1, 2);
        l0r = l0r * corr0 + rs0;
        l1r = l1r * corr1 + rs1;
        m0r = mn0; m1r = mn1;
        #pragma unroll
        for (int j = 0; j < 8; j++) {
            o[j][0] *= corr0; o[j][1] *= corr0;
            o[j][2] *= corr1; o[j][3] *= corr1;
        }

        // ---- O += P V (both single fp16) ----
        #pragma unroll
        for (int kt = 0; kt < 4; kt++) {
            uint32_t ph[4];
            ph[0] = pack_f16(s[2 * kt][0],     s[2 * kt][1]);
            ph[1] = pack_f16(s[2 * kt][2],     s[2 * kt][3]);
            ph[2] = pack_f16(s[2 * kt + 1][0], s[2 * kt + 1][1]);
            ph[3] = pack_f16(s[2 * kt + 1][2], s[2 * kt + 1][3]);
            #pragma unroll
            for (int dn = 0; dn < 4; dn++) {
                uint32_t a = so + (uint32_t)(ATILE + (kt * 16 + lra) * ATS +
                                             dn * 16 + kca) * 2;
                uint32_t v4[4];
                ldsm4t(v4, a);
                mma16816(o[2 * dn],     ph, v4[0], v4[1]);
                mma16816(o[2 * dn + 1], ph, v4[2], v4[3]);
            }
        }
    }

    // ---- epilogue: normalize and write single-fp16 O ----
    const float il0 = 1.0f / l0r, il1 = 1.0f / l1r;
    const int r0 = i0 + warp * 16 + (lane >> 2);
    #pragma unroll
    for (int j = 0; j < 8; j++) {
        int col = gcol + j * 8 + (lane & 3) * 2;
        *(uint32_t*)&Oh[(grow + r0) * CD + col] =
            pack_f16(o[j][0] * il0, o[j][1] * il0);
        *(uint32_t*)&Oh[(grow + r0 + 8) * CD + col] =
            pack_f16(o[j][2] * il1, o[j][3] * il1);
    }
}

// ---------------------------------------------------------------------------

extern "C" void kernel_launch(void* const* d_in, const int* in_sizes, int n_in,
                              void* d_out, int out_size) {
    const float* x  = (const float*)d_in[0];
    const float* Wq = (const float*)d_in[1];
    const float* Wk = (const float*)d_in[2];
    const float* Wv = (const float*)d_in[3];
    const float* Wo = (const float*)d_in[4];
    float* out = (float*)d_out;

    __half *xh, *qh, *kh, *vh, *oh, *wh;
    cudaGetSymbolAddress((void**)&xh, g_xh);
    cudaGetSymbolAddress((void**)&qh, g_qh);
    cudaGetSymbolAddress((void**)&kh, g_kh);
    cudaGetSymbolAddress((void**)&vh, g_vh);
    cudaGetSymbolAddress((void**)&oh, g_oh);
    cudaGetSymbolAddress((void**)&wh, g_wh);

    cudaFuncSetAttribute(gemm_f16<0>,
                         cudaFuncAttributeMaxDynamicSharedMemorySize, QSMEM);
    cudaFuncSetAttribute(gemm_f16<1>,
                         cudaFuncAttributeMaxDynamicSharedMemorySize, QSMEM);
    cudaFuncSetAttribute(attn_mma,
                         cudaFuncAttributeMaxDynamicSharedMemorySize, ATT_SMEM);

    const size_t CC = (size_t)CD * CD;
    const int n4x = MD * CD / 4;

    conv_kernel<<<n4x / 256, 256>>>(x, xh, n4x);
    conv4_kernel<<<4096, 256>>>(Wq, Wk, Wv, Wo, wh);

    gemm_f16<0><<<dim3(24, MD / 128), 256, QSMEM>>>(xh, wh, qh, kh, vh, nullptr);

    attn_mma<<<dim3(TD / 128, BD * NH), 256, ATT_SMEM>>>(qh, kh, vh, oh);

    gemm_f16<1><<<dim3(CD / 128, MD / 128), 256, QSMEM>>>(
        oh, wh + 3 * CC, nullptr, nullptr, nullptr, out);
}